// round 2
// baseline (speedup 1.0000x reference)
#include <cuda_runtime.h>
#include <cstdint>
#include <cstdio>

// ---------------------------------------------------------------------------
// LiBNet forward, batch 512.
// Layouts: all intermediates NHWC (channel fastest). Activations after each
// binarize stored as int8 sign in {-1,0,1}. Binary convs computed in exact
// integer math (dp4a for the 1x1 convs).
// ---------------------------------------------------------------------------

#define BATCH 512

// Scratch (device globals; no allocation allowed)
__device__ float  g_y1[512u*1024u*64u];   // conv1 out  [b,32,32,64]   134MB
__device__ int8_t g_a1[512u*256u*64u];    // sign(pool(bn1)) [b,16,16,64]
__device__ float  g_y2[512u*256u*64u];    // conv2_1 out [b,16,16,64]
__device__ int8_t g_a2[512u*256u*64u];    // sign(bn2_1)
__device__ float  g_y3[512u*256u*256u];   // conv2_2 out [b,16,16,256] 134MB
__device__ int8_t g_a3[512u*64u*256u];    // sign(pool(bn2_2)) [b,8,8,256]
__device__ float  g_y4[512u*64u*256u];    // conv3_1 out
__device__ int8_t g_a4[512u*64u*256u];    // sign(bn3_1)
__device__ float  g_y5[512u*64u*256u];    // conv3_2 out
__device__ int8_t g_wp2[256*64];          // sign(w2_2)
__device__ int8_t g_wp3[256*256];         // sign(w3_2)
__device__ float  g_part[65536*2];        // stats partials [slice][c][2]
__device__ float  g_mean[256];
__device__ float  g_scale[256];
__device__ float  g_fcwr[16384*10];       // fc_w reordered to NHWC-flatten

// ---------------------------------------------------------------------------
// conv1: x [b,3,32,32] NCHW float, pad (t1,b2,l1,r2), 4x4 binarized weights,
// out NHWC [b,32,32,64].
// block: 256 threads = (c 0..63, xq 0..3); one (b, oy) row per block.
// ---------------------------------------------------------------------------
__global__ void conv1_kernel(const float* __restrict__ x,
                             const float* __restrict__ w1,
                             float* __restrict__ y1) {
    int b = blockIdx.y, oy = blockIdx.x;
    int tid = threadIdx.x;
    int c = tid & 63, xq = tid >> 6;

    __shared__ float xs[3][4][36];  // [ci][row][col = ix+1], ix in -1..34

    for (int i = tid; i < 3 * 4 * 36; i += 256) {
        int col = i % 36;
        int r   = (i / 36) % 4;
        int ci  = i / 144;
        int ix = col - 1, iy = oy - 1 + r;
        float v = 0.f;
        if (ix >= 0 && ix < 32 && iy >= 0 && iy < 32)
            v = x[(((size_t)b * 3 + ci) * 32 + iy) * 32 + ix];
        xs[ci][r][col] = v;
    }

    float wr[48];
#pragma unroll
    for (int k = 0; k < 48; k++) {
        float wv = w1[c * 48 + k];
        wr[k] = (wv > 0.f) ? 1.f : ((wv < 0.f) ? -1.f : 0.f);
    }
    __syncthreads();

    for (int j = 0; j < 8; j++) {
        int ox = xq * 8 + j;
        float acc = 0.f;
#pragma unroll
        for (int ci = 0; ci < 3; ci++)
#pragma unroll
            for (int kh = 0; kh < 4; kh++)
#pragma unroll
                for (int kw = 0; kw < 4; kw++)
                    acc += wr[ci * 16 + kh * 4 + kw] * xs[ci][kh][ox + kw];
        y1[((((size_t)b * 32 + oy) * 32 + ox) * 64) + c] = acc;
    }
}

// ---------------------------------------------------------------------------
// Stats: per-channel sum / sumsq partials over NHWC tensor [P, C].
// grid.x = 128 blocks, 256 threads. sub-slices = 256/C.
// ---------------------------------------------------------------------------
__global__ void stats_partial_kernel(const float* __restrict__ y, int P, int C) {
    int c = threadIdx.x % C;
    int q = threadIdx.x / C;
    int sub = 256 / C;
    int slice = blockIdx.x * sub + q;
    int per = P / (128 * sub);
    const float* base = y + (size_t)slice * per * C;
    float s1 = 0.f, s2 = 0.f;
    for (int p = 0; p < per; p++) {
        float v = base[(size_t)p * C + c];
        s1 += v;
        s2 += v * v;
    }
    g_part[(slice * C + c) * 2]     = s1;
    g_part[(slice * C + c) * 2 + 1] = s2;
}

// finalize: compute mean and power-of-two-snapped scale (shift-BN), fp64.
__global__ void finalize_kernel(const float* __restrict__ gamma, int C, int P,
                                int nslices) {
    int c = threadIdx.x;
    if (c >= C) return;
    double s1 = 0.0, s2 = 0.0;
    for (int s = 0; s < nslices; s++) {
        s1 += (double)g_part[(s * C + c) * 2];
        s2 += (double)g_part[(s * C + c) * 2 + 1];
    }
    double mean = s1 / (double)P;
    double var  = s2 / (double)P - mean * mean;
    double inv  = (double)gamma[c] / sqrt(var + 1e-5);
    double sh   = rint(log2(fabs(inv) + 1e-12));
    if (sh > 4.0) sh = 4.0;
    if (sh < -4.0) sh = -4.0;
    double sgn = (inv > 0.0) ? 1.0 : ((inv < 0.0) ? -1.0 : 0.0);
    g_mean[c]  = (float)mean;
    g_scale[c] = (float)(sgn * exp2(sh));
}

// ---------------------------------------------------------------------------
// BN apply + 2x2 maxpool + sign  (NHWC in [b,H,H,C] -> int8 [b,H/2,H/2,C])
// ---------------------------------------------------------------------------
__global__ void bn_pool_sign_kernel(const float* __restrict__ y,
                                    int8_t* __restrict__ out,
                                    const float* __restrict__ beta,
                                    int H, int C, int total) {
    int idx = blockIdx.x * 256 + threadIdx.x;
    if (idx >= total) return;
    int Ho = H >> 1;
    int c = idx % C;
    int t = idx / C;
    int ox = t % Ho; t /= Ho;
    int oy = t % Ho;
    int b  = t / Ho;
    float m = g_mean[c], s = g_scale[c], bt = beta[c];
    size_t base = (((size_t)b * H + 2 * oy) * H + 2 * ox) * C + c;
    float v0 = (y[base] - m) * s + bt;
    float v1 = (y[base + C] - m) * s + bt;
    float v2 = (y[base + (size_t)H * C] - m) * s + bt;
    float v3 = (y[base + (size_t)H * C + C] - m) * s + bt;
    float r = fmaxf(fmaxf(v0, v1), fmaxf(v2, v3));
    out[idx] = (int8_t)((r > 0.f) ? 1 : ((r < 0.f) ? -1 : 0));
}

// BN apply + sign, elementwise NHWC
__global__ void bn_sign_kernel(const float* __restrict__ y,
                               int8_t* __restrict__ out,
                               const float* __restrict__ beta,
                               int C, int total) {
    int idx = blockIdx.x * 256 + threadIdx.x;
    if (idx >= total) return;
    int c = idx % C;
    float v = (y[idx] - g_mean[c]) * g_scale[c] + beta[c];
    out[idx] = (int8_t)((v > 0.f) ? 1 : ((v < 0.f) ? -1 : 0));
}

// ---------------------------------------------------------------------------
// Grouped 4x4 binary conv (2 in-ch per group, out ch c uses in ch {c&~1, c|1})
// in: int8 NHWC [b,H,H,C] (zero pad t1,b2,l1,r2), out float NHWC [b,H,H,C]
// block 256 threads handles one (b, oy) output row.
// ---------------------------------------------------------------------------
template <int H, int C>
__global__ void conv_grp_kernel(const int8_t* __restrict__ a,
                                const float* __restrict__ w,
                                float* __restrict__ out) {
    int b = blockIdx.y, oy = blockIdx.x;
    int tid = threadIdx.x;
    constexpr int PW = H + 3;  // cols ix -1 .. H+1 -> col = ix+1
    __shared__ __align__(16) int8_t as[4][PW][C];

    const int8_t* abase = a + (size_t)b * H * H * C;
    int total4 = (4 * PW * C) / 4;
    for (int i = tid; i < total4; i += 256) {
        int e = i * 4;
        int cc = e % C;
        int col = (e / C) % PW;
        int r = e / (C * PW);
        int ix = col - 1, iy = oy - 1 + r;
        int v = 0;
        if (ix >= 0 && ix < H && iy >= 0 && iy < H)
            v = *(const int*)(abase + ((size_t)iy * H + ix) * C + cc);
        *(int*)(&as[r][col][cc]) = v;
    }

    int c = tid % C;
    int xq = tid / C;
    int g2 = c & ~1;
    int wsgn[32];
    const float* wc = w + (size_t)c * 32;
#pragma unroll
    for (int k = 0; k < 32; k++) {
        float wv = wc[k];
        wsgn[k] = (wv > 0.f) - (wv < 0.f);
    }
    __syncthreads();

    constexpr int SPAN = (H * C) / 256;
    for (int j = 0; j < SPAN; j++) {
        int ox = xq * SPAN + j;
        int acc = 0;
#pragma unroll
        for (int l = 0; l < 2; l++)
#pragma unroll
            for (int kh = 0; kh < 4; kh++)
#pragma unroll
                for (int kw = 0; kw < 4; kw++)
                    acc += wsgn[l * 16 + kh * 4 + kw] * (int)as[kh][ox + kw][g2 + l];
        out[(((size_t)b * H + oy) * H + ox) * C + c] = (float)acc;
    }
}

// pack sign of weights into int8
__global__ void pack_sign_kernel(const float* __restrict__ w,
                                 int8_t* __restrict__ dst, int n) {
    int i = blockIdx.x * 256 + threadIdx.x;
    if (i >= n) return;
    float v = w[i];
    dst[i] = (int8_t)((v > 0.f) ? 1 : ((v < 0.f) ? -1 : 0));
}

// ---------------------------------------------------------------------------
// 1x1 binary conv as GEMM with dp4a.
// gemm64: a [P,64] int8 x w [256,64] -> out [P,256] float. 128 pos per block.
// ---------------------------------------------------------------------------
__global__ void gemm64_kernel(const int8_t* __restrict__ a,
                              const int8_t* __restrict__ wp,
                              float* __restrict__ out) {
    __shared__ __align__(16) int as[128][16];
    int c = threadIdx.x;
    int wr[16];
    const int* w4 = (const int*)wp + c * 16;
#pragma unroll
    for (int k = 0; k < 16; k++) wr[k] = w4[k];
    size_t p0 = (size_t)blockIdx.x * 128;
    const int* a4 = (const int*)(a + p0 * 64);
    for (int i = threadIdx.x; i < 2048; i += 256) as[i >> 4][i & 15] = a4[i];
    __syncthreads();
    for (int p = 0; p < 128; p++) {
        int acc = 0;
        const int4* av = (const int4*)as[p];
#pragma unroll
        for (int k4 = 0; k4 < 4; k4++) {
            int4 v = av[k4];
            acc = __dp4a(v.x, wr[k4 * 4 + 0], acc);
            acc = __dp4a(v.y, wr[k4 * 4 + 1], acc);
            acc = __dp4a(v.z, wr[k4 * 4 + 2], acc);
            acc = __dp4a(v.w, wr[k4 * 4 + 3], acc);
        }
        out[(p0 + p) * 256 + c] = (float)acc;
    }
}

// gemm256: a [P,256] int8 x w [256,256] -> out [P,256] float. 64 pos per block.
__global__ void gemm256_kernel(const int8_t* __restrict__ a,
                               const int8_t* __restrict__ wp,
                               float* __restrict__ out) {
    __shared__ __align__(16) int as[64][64];
    int c = threadIdx.x;
    int wr[64];
    const int* w4 = (const int*)wp + c * 64;
#pragma unroll
    for (int k = 0; k < 64; k++) wr[k] = w4[k];
    size_t p0 = (size_t)blockIdx.x * 64;
    const int* a4 = (const int*)(a + p0 * 256);
    for (int i = threadIdx.x; i < 4096; i += 256) as[i >> 6][i & 63] = a4[i];
    __syncthreads();
    for (int p = 0; p < 64; p++) {
        int acc = 0;
        const int4* av = (const int4*)as[p];
#pragma unroll
        for (int k4 = 0; k4 < 16; k4++) {
            int4 v = av[k4];
            acc = __dp4a(v.x, wr[k4 * 4 + 0], acc);
            acc = __dp4a(v.y, wr[k4 * 4 + 1], acc);
            acc = __dp4a(v.z, wr[k4 * 4 + 2], acc);
            acc = __dp4a(v.w, wr[k4 * 4 + 3], acc);
        }
        out[(p0 + p) * 256 + c] = (float)acc;
    }
}

// ---------------------------------------------------------------------------
// FC: reorder fc_w to NHWC-flatten order, then BN(y5) . fcwr per batch elem.
// ---------------------------------------------------------------------------
__global__ void fcw_reorder_kernel(const float* __restrict__ fcw,
                                   float* __restrict__ fcwr) {
    int i = blockIdx.x * 256 + threadIdx.x;  // i = e*10 + n, e = hw*256 + c
    if (i >= 16384 * 10) return;
    int n = i % 10;
    int e = i / 10;
    int c = e % 256, hw = e / 256;
    fcwr[i] = fcw[n * 16384 + c * 64 + hw];
}

__global__ void fc_kernel(const float* __restrict__ y5,
                          const float* __restrict__ fcwr,
                          const float* __restrict__ fc_b,
                          const float* __restrict__ beta,
                          float* __restrict__ out) {
    int b = blockIdx.x;
    float acc[10];
#pragma unroll
    for (int n = 0; n < 10; n++) acc[n] = 0.f;
    const float* yb = y5 + (size_t)b * 16384;
    for (int i = threadIdx.x; i < 16384; i += 256) {
        int c = i & 255;
        float v = (yb[i] - g_mean[c]) * g_scale[c] + beta[c];
        const float* wr = fcwr + (size_t)i * 10;
#pragma unroll
        for (int n = 0; n < 10; n++) acc[n] += v * wr[n];
    }
    __shared__ float red[256];
    for (int n = 0; n < 10; n++) {
        red[threadIdx.x] = acc[n];
        __syncthreads();
        for (int s = 128; s > 0; s >>= 1) {
            if (threadIdx.x < s) red[threadIdx.x] += red[threadIdx.x + s];
            __syncthreads();
        }
        if (threadIdx.x == 0) out[b * 10 + n] = red[0] + fc_b[n];
        __syncthreads();
    }
}

// ---------------------------------------------------------------------------
extern "C" void kernel_launch(void* const* d_in, const int* in_sizes, int n_in,
                              void* d_out, int out_size) {
    const float* x    = (const float*)d_in[0];
    const float* w1   = (const float*)d_in[1];
    const float* g1   = (const float*)d_in[2];
    const float* b1   = (const float*)d_in[3];
    const float* w2_1 = (const float*)d_in[4];
    const float* g2_1 = (const float*)d_in[5];
    const float* b2_1 = (const float*)d_in[6];
    const float* w2_2 = (const float*)d_in[7];
    const float* g2_2 = (const float*)d_in[8];
    const float* b2_2 = (const float*)d_in[9];
    const float* w3_1 = (const float*)d_in[10];
    const float* g3_1 = (const float*)d_in[11];
    const float* b3_1 = (const float*)d_in[12];
    const float* w3_2 = (const float*)d_in[13];
    const float* g3_2 = (const float*)d_in[14];
    const float* b3_2 = (const float*)d_in[15];
    const float* fcw  = (const float*)d_in[16];
    const float* fcb  = (const float*)d_in[17];
    float* out = (float*)d_out;

    float *y1, *y2, *y3, *y4, *y5, *fcwr;
    int8_t *a1, *a2, *a3, *a4, *wp2, *wp3;
    cudaGetSymbolAddress((void**)&y1, g_y1);
    cudaGetSymbolAddress((void**)&y2, g_y2);
    cudaGetSymbolAddress((void**)&y3, g_y3);
    cudaGetSymbolAddress((void**)&y4, g_y4);
    cudaGetSymbolAddress((void**)&y5, g_y5);
    cudaGetSymbolAddress((void**)&a1, g_a1);
    cudaGetSymbolAddress((void**)&a2, g_a2);
    cudaGetSymbolAddress((void**)&a3, g_a3);
    cudaGetSymbolAddress((void**)&a4, g_a4);
    cudaGetSymbolAddress((void**)&wp2, g_wp2);
    cudaGetSymbolAddress((void**)&wp3, g_wp3);
    cudaGetSymbolAddress((void**)&fcwr, g_fcwr);

    // Stage 1: conv1 + bn1 + pool + sign
    conv1_kernel<<<dim3(32, BATCH), 256>>>(x, w1, y1);
    stats_partial_kernel<<<128, 256>>>(y1, 512 * 1024, 64);
    finalize_kernel<<<1, 256>>>(g1, 64, 512 * 1024, 512);
    bn_pool_sign_kernel<<<(512 * 256 * 64) / 256, 256>>>(y1, a1, b1, 32, 64,
                                                         512 * 256 * 64);

    // Stage 2: grouped conv2_1 + bn + sign; 1x1 conv2_2 + bn + pool + sign
    conv_grp_kernel<16, 64><<<dim3(16, BATCH), 256>>>(a1, w2_1, y2);
    stats_partial_kernel<<<128, 256>>>(y2, 512 * 256, 64);
    finalize_kernel<<<1, 256>>>(g2_1, 64, 512 * 256, 512);
    bn_sign_kernel<<<(512 * 256 * 64) / 256, 256>>>(y2, a2, b2_1, 64,
                                                    512 * 256 * 64);

    pack_sign_kernel<<<64, 256>>>(w2_2, wp2, 256 * 64);
    gemm64_kernel<<<(512 * 256) / 128, 256>>>(a2, wp2, y3);
    stats_partial_kernel<<<128, 256>>>(y3, 512 * 256, 256);
    finalize_kernel<<<1, 256>>>(g2_2, 256, 512 * 256, 128);
    bn_pool_sign_kernel<<<(512 * 64 * 256) / 256, 256>>>(y3, a3, b2_2, 16, 256,
                                                         512 * 64 * 256);

    // Stage 3: grouped conv3_1 + bn + sign; 1x1 conv3_2 + bn
    conv_grp_kernel<8, 256><<<dim3(8, BATCH), 256>>>(a3, w3_1, y4);
    stats_partial_kernel<<<128, 256>>>(y4, 512 * 64, 256);
    finalize_kernel<<<1, 256>>>(g3_1, 256, 512 * 64, 128);
    bn_sign_kernel<<<(512 * 64 * 256) / 256, 256>>>(y4, a4, b3_1, 256,
                                                    512 * 64 * 256);

    pack_sign_kernel<<<256, 256>>>(w3_2, wp3, 256 * 256);
    gemm256_kernel<<<(512 * 64) / 64, 256>>>(a4, wp3, y5);
    stats_partial_kernel<<<128, 256>>>(y5, 512 * 64, 256);
    finalize_kernel<<<1, 256>>>(g3_2, 256, 512 * 64, 128);

    // FC (bn3_2 fused)
    fcw_reorder_kernel<<<640, 256>>>(fcw, fcwr);
    fc_kernel<<<BATCH, 256>>>(y5, fcwr, fcb, b3_2, out);
}

// round 3
// speedup vs baseline: 1.3462x; 1.3462x over previous
#include <cuda_runtime.h>
#include <cstdint>
#include <cstdio>

// ---------------------------------------------------------------------------
// LiBNet forward, batch 512.  Round 3: fused stats in producers, parallel
// reduce+finalize, vectorized BN kernels, coalesced multi-batch FC.
// Layouts: all intermediates NHWC. Binarized activations int8 {-1,0,1}.
// ---------------------------------------------------------------------------

#define BATCH 512

// Scratch (device globals; no allocation allowed)
__device__ float  g_y1[512u*1024u*64u];   // conv1 out  [b,32,32,64]
__device__ int8_t g_a1[512u*256u*64u];    // sign(pool(bn1)) [b,16,16,64]
__device__ float  g_y2[512u*256u*64u];    // conv2_1 out
__device__ int8_t g_a2[512u*256u*64u];    // sign(bn2_1)
__device__ float  g_y3[512u*256u*256u];   // conv2_2 out [b,16,16,256]
__device__ int8_t g_a3[512u*64u*256u];    // sign(pool(bn2_2)) [b,8,8,256]
__device__ float  g_y4[512u*64u*256u];    // conv3_1 out
__device__ int8_t g_a4[512u*64u*256u];    // sign(bn3_1)
__device__ float  g_y5[512u*64u*256u];    // conv3_2 out
__device__ int8_t g_wp2[256*64];          // sign(w2_2)
__device__ int8_t g_wp3[256*256];         // sign(w3_2)
__device__ float  g_part[2097152];        // stats partials [slice][c][2]
__device__ float  g_mean[256];
__device__ float  g_scale[256];
__device__ float  g_fcwr[16384*10];       // fc_w n-major over NHWC-flatten

// ---------------------------------------------------------------------------
// conv1: x [b,3,32,32] NCHW float, pad (t1,b2,l1,r2), 4x4 binarized weights,
// out NHWC [b,32,32,64].  Fused per-block channel stats -> g_part[slice][c].
// block: 256 threads = (c 0..63, xq 0..3); one (b, oy) row per block.
// ---------------------------------------------------------------------------
__global__ void conv1_kernel(const float* __restrict__ x,
                             const float* __restrict__ w1,
                             float* __restrict__ y1) {
    int b = blockIdx.y, oy = blockIdx.x;
    int tid = threadIdx.x;
    int c = tid & 63, xq = tid >> 6;

    __shared__ float xs[3][4][36];  // [ci][row][col = ix+1]
    __shared__ float2 sred[256];

    for (int i = tid; i < 3 * 4 * 36; i += 256) {
        int col = i % 36;
        int r   = (i / 36) % 4;
        int ci  = i / 144;
        int ix = col - 1, iy = oy - 1 + r;
        float v = 0.f;
        if (ix >= 0 && ix < 32 && iy >= 0 && iy < 32)
            v = x[(((size_t)b * 3 + ci) * 32 + iy) * 32 + ix];
        xs[ci][r][col] = v;
    }

    float wr[48];
#pragma unroll
    for (int k = 0; k < 48; k++) {
        float wv = w1[c * 48 + k];
        wr[k] = (wv > 0.f) ? 1.f : ((wv < 0.f) ? -1.f : 0.f);
    }
    __syncthreads();

    float acc[8];
#pragma unroll
    for (int j = 0; j < 8; j++) acc[j] = 0.f;

#pragma unroll
    for (int ci = 0; ci < 3; ci++) {
#pragma unroll
        for (int kh = 0; kh < 4; kh++) {
            float rx[11];
#pragma unroll
            for (int t = 0; t < 11; t++) rx[t] = xs[ci][kh][xq * 8 + t];
#pragma unroll
            for (int kw = 0; kw < 4; kw++) {
                float wv = wr[ci * 16 + kh * 4 + kw];
#pragma unroll
                for (int j = 0; j < 8; j++) acc[j] += wv * rx[j + kw];
            }
        }
    }

    float s1 = 0.f, s2 = 0.f;
    size_t obase = (((size_t)b * 32 + oy) * 32 + xq * 8) * 64 + c;
#pragma unroll
    for (int j = 0; j < 8; j++) {
        y1[obase + (size_t)j * 64] = acc[j];
        s1 += acc[j];
        s2 += acc[j] * acc[j];
    }

    // reduce over xq (4 groups) -> g_part[slice=bid][c]
    sred[tid] = make_float2(s1, s2);
    __syncthreads();
    if (tid < 64) {
        float2 a = sred[tid], b1 = sred[tid + 64], c1 = sred[tid + 128],
               d1 = sred[tid + 192];
        int slice = b * 32 + oy;
        g_part[(slice * 64 + tid) * 2]     = a.x + b1.x + c1.x + d1.x;
        g_part[(slice * 64 + tid) * 2 + 1] = a.y + b1.y + c1.y + d1.y;
    }
}

// ---------------------------------------------------------------------------
// Reduce partials over slices + shift-BN finalize. One block per channel.
// ---------------------------------------------------------------------------
template <int C>
__global__ void reduce_finalize_kernel(const float* __restrict__ gamma,
                                       int nslices, int P) {
    int c = blockIdx.x;
    int tid = threadIdx.x;
    float s1 = 0.f, s2 = 0.f;
    for (int s = tid; s < nslices; s += 256) {
        s1 += g_part[(s * C + c) * 2];
        s2 += g_part[(s * C + c) * 2 + 1];
    }
    __shared__ double sd1[256], sd2[256];
    sd1[tid] = (double)s1;
    sd2[tid] = (double)s2;
    __syncthreads();
    for (int s = 128; s > 0; s >>= 1) {
        if (tid < s) {
            sd1[tid] += sd1[tid + s];
            sd2[tid] += sd2[tid + s];
        }
        __syncthreads();
    }
    if (tid == 0) {
        double mean = sd1[0] / (double)P;
        double var  = sd2[0] / (double)P - mean * mean;
        double inv  = (double)gamma[c] / sqrt(var + 1e-5);
        double sh   = rint(log2(fabs(inv) + 1e-12));
        if (sh > 4.0) sh = 4.0;
        if (sh < -4.0) sh = -4.0;
        double sgn = (inv > 0.0) ? 1.0 : ((inv < 0.0) ? -1.0 : 0.0);
        g_mean[c]  = (float)mean;
        g_scale[c] = (float)(sgn * exp2(sh));
    }
}

// ---------------------------------------------------------------------------
// BN apply + 2x2 maxpool + sign, 4 channels per thread (float4 / char4).
// ---------------------------------------------------------------------------
__global__ void bn_pool_sign4_kernel(const float* __restrict__ y,
                                     int8_t* __restrict__ out,
                                     const float* __restrict__ beta,
                                     int H, int C, int total4) {
    int idx = blockIdx.x * 256 + threadIdx.x;
    if (idx >= total4) return;
    int e = idx * 4;
    int Ho = H >> 1;
    int c = e % C;
    int t = e / C;
    int ox = t % Ho; t /= Ho;
    int oy = t % Ho;
    int b  = t / Ho;
    float4 m  = *(const float4*)(g_mean + c);
    float4 s  = *(const float4*)(g_scale + c);
    float4 bt = *(const float4*)(beta + c);
    size_t base = (((size_t)b * H + 2 * oy) * H + 2 * ox) * C + c;
    float4 v0 = *(const float4*)(y + base);
    float4 v1 = *(const float4*)(y + base + C);
    float4 v2 = *(const float4*)(y + base + (size_t)H * C);
    float4 v3 = *(const float4*)(y + base + (size_t)H * C + C);
    float r0 = fmaxf(fmaxf(v0.x, v1.x), fmaxf(v2.x, v3.x));
    float r1 = fmaxf(fmaxf(v0.y, v1.y), fmaxf(v2.y, v3.y));
    float r2 = fmaxf(fmaxf(v0.z, v1.z), fmaxf(v2.z, v3.z));
    float r3 = fmaxf(fmaxf(v0.w, v1.w), fmaxf(v2.w, v3.w));
    r0 = (r0 - m.x) * s.x + bt.x;
    r1 = (r1 - m.y) * s.y + bt.y;
    r2 = (r2 - m.z) * s.z + bt.z;
    r3 = (r3 - m.w) * s.w + bt.w;
    char4 o;
    o.x = (char)((r0 > 0.f) ? 1 : ((r0 < 0.f) ? -1 : 0));
    o.y = (char)((r1 > 0.f) ? 1 : ((r1 < 0.f) ? -1 : 0));
    o.z = (char)((r2 > 0.f) ? 1 : ((r2 < 0.f) ? -1 : 0));
    o.w = (char)((r3 > 0.f) ? 1 : ((r3 < 0.f) ? -1 : 0));
    ((char4*)out)[idx] = o;
}

// NOTE: pool-then-BN == BN-then-pool only when scale>0; handle sign via
// per-channel select: if scale<0 the max becomes min. Do BN before max to be
// exact:  (kept exact above is WRONG for negative scale) -> use exact version:
__global__ void bn_pool_sign4_exact_kernel(const float* __restrict__ y,
                                           int8_t* __restrict__ out,
                                           const float* __restrict__ beta,
                                           int H, int C, int total4) {
    int idx = blockIdx.x * 256 + threadIdx.x;
    if (idx >= total4) return;
    int e = idx * 4;
    int Ho = H >> 1;
    int c = e % C;
    int t = e / C;
    int ox = t % Ho; t /= Ho;
    int oy = t % Ho;
    int b  = t / Ho;
    float4 m  = *(const float4*)(g_mean + c);
    float4 s  = *(const float4*)(g_scale + c);
    float4 bt = *(const float4*)(beta + c);
    size_t base = (((size_t)b * H + 2 * oy) * H + 2 * ox) * C + c;
    float4 v0 = *(const float4*)(y + base);
    float4 v1 = *(const float4*)(y + base + C);
    float4 v2 = *(const float4*)(y + base + (size_t)H * C);
    float4 v3 = *(const float4*)(y + base + (size_t)H * C + C);
    float r0 = fmaxf(fmaxf((v0.x - m.x) * s.x, (v1.x - m.x) * s.x),
                     fmaxf((v2.x - m.x) * s.x, (v3.x - m.x) * s.x)) + bt.x;
    float r1 = fmaxf(fmaxf((v0.y - m.y) * s.y, (v1.y - m.y) * s.y),
                     fmaxf((v2.y - m.y) * s.y, (v3.y - m.y) * s.y)) + bt.y;
    float r2 = fmaxf(fmaxf((v0.z - m.z) * s.z, (v1.z - m.z) * s.z),
                     fmaxf((v2.z - m.z) * s.z, (v3.z - m.z) * s.z)) + bt.z;
    float r3 = fmaxf(fmaxf((v0.w - m.w) * s.w, (v1.w - m.w) * s.w),
                     fmaxf((v2.w - m.w) * s.w, (v3.w - m.w) * s.w)) + bt.w;
    char4 o;
    o.x = (char)((r0 > 0.f) ? 1 : ((r0 < 0.f) ? -1 : 0));
    o.y = (char)((r1 > 0.f) ? 1 : ((r1 < 0.f) ? -1 : 0));
    o.z = (char)((r2 > 0.f) ? 1 : ((r2 < 0.f) ? -1 : 0));
    o.w = (char)((r3 > 0.f) ? 1 : ((r3 < 0.f) ? -1 : 0));
    ((char4*)out)[idx] = o;
}

// BN apply + sign, 4 channels per thread
__global__ void bn_sign4_kernel(const float* __restrict__ y,
                                int8_t* __restrict__ out,
                                const float* __restrict__ beta,
                                int C, int total4) {
    int idx = blockIdx.x * 256 + threadIdx.x;
    if (idx >= total4) return;
    int c = (idx * 4) % C;
    float4 m  = *(const float4*)(g_mean + c);
    float4 s  = *(const float4*)(g_scale + c);
    float4 bt = *(const float4*)(beta + c);
    float4 v = ((const float4*)y)[idx];
    float r0 = (v.x - m.x) * s.x + bt.x;
    float r1 = (v.y - m.y) * s.y + bt.y;
    float r2 = (v.z - m.z) * s.z + bt.z;
    float r3 = (v.w - m.w) * s.w + bt.w;
    char4 o;
    o.x = (char)((r0 > 0.f) ? 1 : ((r0 < 0.f) ? -1 : 0));
    o.y = (char)((r1 > 0.f) ? 1 : ((r1 < 0.f) ? -1 : 0));
    o.z = (char)((r2 > 0.f) ? 1 : ((r2 < 0.f) ? -1 : 0));
    o.w = (char)((r3 > 0.f) ? 1 : ((r3 < 0.f) ? -1 : 0));
    ((char4*)out)[idx] = o;
}

// ---------------------------------------------------------------------------
// Grouped 4x4 binary conv, fused stats.
// ---------------------------------------------------------------------------
template <int H, int C>
__global__ void conv_grp_kernel(const int8_t* __restrict__ a,
                                const float* __restrict__ w,
                                float* __restrict__ out) {
    int b = blockIdx.y, oy = blockIdx.x;
    int tid = threadIdx.x;
    constexpr int PW = H + 3;
    __shared__ __align__(16) int8_t as[4][PW][C];
    __shared__ float2 sred[256];

    const int8_t* abase = a + (size_t)b * H * H * C;
    int total4 = (4 * PW * C) / 4;
    for (int i = tid; i < total4; i += 256) {
        int e = i * 4;
        int cc = e % C;
        int col = (e / C) % PW;
        int r = e / (C * PW);
        int ix = col - 1, iy = oy - 1 + r;
        int v = 0;
        if (ix >= 0 && ix < H && iy >= 0 && iy < H)
            v = *(const int*)(abase + ((size_t)iy * H + ix) * C + cc);
        *(int*)(&as[r][col][cc]) = v;
    }

    int c = tid % C;
    int xq = tid / C;
    int g2 = c & ~1;
    int wsgn[32];
    const float* wc = w + (size_t)c * 32;
#pragma unroll
    for (int k = 0; k < 32; k++) {
        float wv = wc[k];
        wsgn[k] = (wv > 0.f) - (wv < 0.f);
    }
    __syncthreads();

    float s1 = 0.f, s2 = 0.f;
    constexpr int SPAN = (H * C) / 256;
    for (int j = 0; j < SPAN; j++) {
        int ox = xq * SPAN + j;
        int acc = 0;
#pragma unroll
        for (int l = 0; l < 2; l++)
#pragma unroll
            for (int kh = 0; kh < 4; kh++)
#pragma unroll
                for (int kw = 0; kw < 4; kw++)
                    acc += wsgn[l * 16 + kh * 4 + kw] * (int)as[kh][ox + kw][g2 + l];
        float f = (float)acc;
        out[(((size_t)b * H + oy) * H + ox) * C + c] = f;
        s1 += f;
        s2 += f * f;
    }

    int slice = b * gridDim.x + blockIdx.x;
    if (C == 256) {
        g_part[(slice * 256 + c) * 2]     = s1;
        g_part[(slice * 256 + c) * 2 + 1] = s2;
    } else {
        sred[tid] = make_float2(s1, s2);
        __syncthreads();
        if (tid < C) {
            float a1 = 0.f, a2 = 0.f;
            for (int q = 0; q < 256 / C; q++) {
                a1 += sred[q * C + tid].x;
                a2 += sred[q * C + tid].y;
            }
            g_part[(slice * C + tid) * 2]     = a1;
            g_part[(slice * C + tid) * 2 + 1] = a2;
        }
    }
}

// pack sign of weights into int8
__global__ void pack_sign_kernel(const float* __restrict__ w,
                                 int8_t* __restrict__ dst, int n) {
    int i = blockIdx.x * 256 + threadIdx.x;
    if (i >= n) return;
    float v = w[i];
    dst[i] = (int8_t)((v > 0.f) ? 1 : ((v < 0.f) ? -1 : 0));
}

// ---------------------------------------------------------------------------
// 1x1 binary conv as GEMM with dp4a, fused per-thread stats.
// ---------------------------------------------------------------------------
__global__ void gemm64_kernel(const int8_t* __restrict__ a,
                              const int8_t* __restrict__ wp,
                              float* __restrict__ out) {
    __shared__ __align__(16) int as[128][16];
    int c = threadIdx.x;
    int wr[16];
    const int* w4 = (const int*)wp + c * 16;
#pragma unroll
    for (int k = 0; k < 16; k++) wr[k] = w4[k];
    size_t p0 = (size_t)blockIdx.x * 128;
    const int* a4 = (const int*)(a + p0 * 64);
    for (int i = threadIdx.x; i < 2048; i += 256) as[i >> 4][i & 15] = a4[i];
    __syncthreads();
    float s1 = 0.f, s2 = 0.f;
    for (int p = 0; p < 128; p++) {
        int acc = 0;
        const int4* av = (const int4*)as[p];
#pragma unroll
        for (int k4 = 0; k4 < 4; k4++) {
            int4 v = av[k4];
            acc = __dp4a(v.x, wr[k4 * 4 + 0], acc);
            acc = __dp4a(v.y, wr[k4 * 4 + 1], acc);
            acc = __dp4a(v.z, wr[k4 * 4 + 2], acc);
            acc = __dp4a(v.w, wr[k4 * 4 + 3], acc);
        }
        float f = (float)acc;
        out[(p0 + p) * 256 + c] = f;
        s1 += f;
        s2 += f * f;
    }
    g_part[(blockIdx.x * 256 + c) * 2]     = s1;
    g_part[(blockIdx.x * 256 + c) * 2 + 1] = s2;
}

__global__ void gemm256_kernel(const int8_t* __restrict__ a,
                               const int8_t* __restrict__ wp,
                               float* __restrict__ out) {
    __shared__ __align__(16) int as[64][64];
    int c = threadIdx.x;
    int wr[64];
    const int* w4 = (const int*)wp + c * 64;
#pragma unroll
    for (int k = 0; k < 64; k++) wr[k] = w4[k];
    size_t p0 = (size_t)blockIdx.x * 64;
    const int* a4 = (const int*)(a + p0 * 256);
    for (int i = threadIdx.x; i < 4096; i += 256) as[i >> 6][i & 63] = a4[i];
    __syncthreads();
    float s1 = 0.f, s2 = 0.f;
    for (int p = 0; p < 64; p++) {
        int acc = 0;
        const int4* av = (const int4*)as[p];
#pragma unroll
        for (int k4 = 0; k4 < 16; k4++) {
            int4 v = av[k4];
            acc = __dp4a(v.x, wr[k4 * 4 + 0], acc);
            acc = __dp4a(v.y, wr[k4 * 4 + 1], acc);
            acc = __dp4a(v.z, wr[k4 * 4 + 2], acc);
            acc = __dp4a(v.w, wr[k4 * 4 + 3], acc);
        }
        float f = (float)acc;
        out[(p0 + p) * 256 + c] = f;
        s1 += f;
        s2 += f * f;
    }
    g_part[(blockIdx.x * 256 + c) * 2]     = s1;
    g_part[(blockIdx.x * 256 + c) * 2 + 1] = s2;
}

// ---------------------------------------------------------------------------
// FC: fc_w to n-major over NHWC-flatten index; 4 batches per block.
// ---------------------------------------------------------------------------
__global__ void fcw_reorder_kernel(const float* __restrict__ fcw,
                                   float* __restrict__ fcwr) {
    int i = blockIdx.x * 256 + threadIdx.x;  // i = n*16384 + e, e = hw*256 + c
    if (i >= 16384 * 10) return;
    int n = i / 16384;
    int e = i % 16384;
    int c = e & 255, hw = e >> 8;
    fcwr[i] = fcw[n * 16384 + c * 64 + hw];
}

#define FCB 4
__global__ void fc_kernel(const float* __restrict__ y5,
                          const float* __restrict__ fcwr,
                          const float* __restrict__ fc_b,
                          const float* __restrict__ beta,
                          float* __restrict__ out) {
    int b0 = blockIdx.x * FCB;
    int tid = threadIdx.x;
    float acc[FCB][10];
#pragma unroll
    for (int bb = 0; bb < FCB; bb++)
#pragma unroll
        for (int n = 0; n < 10; n++) acc[bb][n] = 0.f;

    for (int i = tid; i < 16384; i += 256) {
        int c = i & 255;
        float m = g_mean[c], s = g_scale[c], bt = beta[c];
        float w[10];
#pragma unroll
        for (int n = 0; n < 10; n++) w[n] = fcwr[n * 16384 + i];
#pragma unroll
        for (int bb = 0; bb < FCB; bb++) {
            float v = (y5[(size_t)(b0 + bb) * 16384 + i] - m) * s + bt;
#pragma unroll
            for (int n = 0; n < 10; n++) acc[bb][n] += v * w[n];
        }
    }

    // warp reduce then cross-warp via smem
    __shared__ float sred[8][FCB * 10];
    int lane = tid & 31, wid = tid >> 5;
#pragma unroll
    for (int bb = 0; bb < FCB; bb++)
#pragma unroll
        for (int n = 0; n < 10; n++) {
            float v = acc[bb][n];
#pragma unroll
            for (int o = 16; o > 0; o >>= 1)
                v += __shfl_xor_sync(0xffffffffu, v, o);
            if (lane == 0) sred[wid][bb * 10 + n] = v;
        }
    __syncthreads();
    if (tid < FCB * 10) {
        float v = 0.f;
#pragma unroll
        for (int w8 = 0; w8 < 8; w8++) v += sred[w8][tid];
        int bb = tid / 10, n = tid % 10;
        out[(b0 + bb) * 10 + n] = v + fc_b[n];
    }
}

// ---------------------------------------------------------------------------
extern "C" void kernel_launch(void* const* d_in, const int* in_sizes, int n_in,
                              void* d_out, int out_size) {
    const float* x    = (const float*)d_in[0];
    const float* w1   = (const float*)d_in[1];
    const float* g1   = (const float*)d_in[2];
    const float* b1   = (const float*)d_in[3];
    const float* w2_1 = (const float*)d_in[4];
    const float* g2_1 = (const float*)d_in[5];
    const float* b2_1 = (const float*)d_in[6];
    const float* w2_2 = (const float*)d_in[7];
    const float* g2_2 = (const float*)d_in[8];
    const float* b2_2 = (const float*)d_in[9];
    const float* w3_1 = (const float*)d_in[10];
    const float* g3_1 = (const float*)d_in[11];
    const float* b3_1 = (const float*)d_in[12];
    const float* w3_2 = (const float*)d_in[13];
    const float* g3_2 = (const float*)d_in[14];
    const float* b3_2 = (const float*)d_in[15];
    const float* fcw  = (const float*)d_in[16];
    const float* fcb  = (const float*)d_in[17];
    float* out = (float*)d_out;

    float *y1, *y2, *y3, *y4, *y5, *fcwr;
    int8_t *a1, *a2, *a3, *a4, *wp2, *wp3;
    cudaGetSymbolAddress((void**)&y1, g_y1);
    cudaGetSymbolAddress((void**)&y2, g_y2);
    cudaGetSymbolAddress((void**)&y3, g_y3);
    cudaGetSymbolAddress((void**)&y4, g_y4);
    cudaGetSymbolAddress((void**)&y5, g_y5);
    cudaGetSymbolAddress((void**)&a1, g_a1);
    cudaGetSymbolAddress((void**)&a2, g_a2);
    cudaGetSymbolAddress((void**)&a3, g_a3);
    cudaGetSymbolAddress((void**)&a4, g_a4);
    cudaGetSymbolAddress((void**)&wp2, g_wp2);
    cudaGetSymbolAddress((void**)&wp3, g_wp3);
    cudaGetSymbolAddress((void**)&fcwr, g_fcwr);

    // weight prep (independent of activations)
    pack_sign_kernel<<<64, 256>>>(w2_2, wp2, 256 * 64);
    pack_sign_kernel<<<256, 256>>>(w3_2, wp3, 256 * 256);
    fcw_reorder_kernel<<<640, 256>>>(fcw, fcwr);

    // Stage 1: conv1 (+stats) -> finalize -> bn+pool+sign
    conv1_kernel<<<dim3(32, BATCH), 256>>>(x, w1, y1);
    reduce_finalize_kernel<64><<<64, 256>>>(g1, 512 * 32, 512 * 1024);
    bn_pool_sign4_exact_kernel<<<(512 * 256 * 64 / 4 + 255) / 256, 256>>>(
        y1, a1, b1, 32, 64, 512 * 256 * 64 / 4);

    // Stage 2
    conv_grp_kernel<16, 64><<<dim3(16, BATCH), 256>>>(a1, w2_1, y2);
    reduce_finalize_kernel<64><<<64, 256>>>(g2_1, 512 * 16, 512 * 256);
    bn_sign4_kernel<<<(512 * 256 * 64 / 4 + 255) / 256, 256>>>(
        y2, a2, b2_1, 64, 512 * 256 * 64 / 4);

    gemm64_kernel<<<(512 * 256) / 128, 256>>>(a2, wp2, y3);
    reduce_finalize_kernel<256><<<256, 256>>>(g2_2, 1024, 512 * 256);
    bn_pool_sign4_exact_kernel<<<(512 * 64 * 256 / 4 + 255) / 256, 256>>>(
        y3, a3, b2_2, 16, 256, 512 * 64 * 256 / 4);

    // Stage 3
    conv_grp_kernel<8, 256><<<dim3(8, BATCH), 256>>>(a3, w3_1, y4);
    reduce_finalize_kernel<256><<<256, 256>>>(g3_1, 512 * 8, 512 * 64);
    bn_sign4_kernel<<<(512 * 64 * 256 / 4 + 255) / 256, 256>>>(
        y4, a4, b3_1, 256, 512 * 64 * 256 / 4);

    gemm256_kernel<<<(512 * 64) / 64, 256>>>(a4, wp3, y5);
    reduce_finalize_kernel<256><<<256, 256>>>(g3_2, 512, 512 * 64);

    // FC (bn3_2 fused)
    fc_kernel<<<BATCH / FCB, 256>>>(y5, fcwr, fcb, b3_2, out);
}

// round 4
// speedup vs baseline: 1.8671x; 1.3869x over previous
#include <cuda_runtime.h>
#include <cstdint>
#include <cstdio>

// ---------------------------------------------------------------------------
// LiBNet forward, batch 512.  Round 4: conv1 weight transpose (kills L1tex
// wavefront storm seen in ncu: L1=96.9%), 4 rows per conv1 block.
// Layouts: all intermediates NHWC. Binarized activations int8 {-1,0,1}.
// ---------------------------------------------------------------------------

#define BATCH 512

// Scratch (device globals; no allocation allowed)
__device__ float  g_y1[512u*1024u*64u];   // conv1 out  [b,32,32,64]
__device__ int8_t g_a1[512u*256u*64u];    // sign(pool(bn1)) [b,16,16,64]
__device__ float  g_y2[512u*256u*64u];    // conv2_1 out
__device__ int8_t g_a2[512u*256u*64u];    // sign(bn2_1)
__device__ float  g_y3[512u*256u*256u];   // conv2_2 out [b,16,16,256]
__device__ int8_t g_a3[512u*64u*256u];    // sign(pool(bn2_2)) [b,8,8,256]
__device__ float  g_y4[512u*64u*256u];    // conv3_1 out
__device__ int8_t g_a4[512u*64u*256u];    // sign(bn3_1)
__device__ float  g_y5[512u*64u*256u];    // conv3_2 out
__device__ float  g_w1s[48*64];           // sign(w1) transposed [k][c]
__device__ int8_t g_wp2[256*64];          // sign(w2_2)
__device__ int8_t g_wp3[256*256];         // sign(w3_2)
__device__ float  g_part[2097152];        // stats partials [slice][c][2]
__device__ float  g_mean[256];
__device__ float  g_scale[256];
__device__ float  g_fcwr[16384*10];       // fc_w n-major over NHWC-flatten

// pack sign of w1 [64,3,4,4] -> transposed float [k=48][c=64]
__global__ void pack_w1_kernel(const float* __restrict__ w1,
                               float* __restrict__ w1s) {
    int i = blockIdx.x * 256 + threadIdx.x;  // i = k*64 + c
    if (i >= 48 * 64) return;
    int c = i & 63, k = i >> 6;
    float v = w1[c * 48 + k];
    w1s[i] = (v > 0.f) ? 1.f : ((v < 0.f) ? -1.f : 0.f);
}

// ---------------------------------------------------------------------------
// conv1: x [b,3,32,32] NCHW float, pad (t1,b2,l1,r2), 4x4 binarized weights,
// out NHWC [b,32,32,64].  4 output rows per block; fused channel stats.
// block: 256 threads = (c 0..63, xq 0..3); grid (8, B).
// ---------------------------------------------------------------------------
__global__ void conv1_kernel(const float* __restrict__ x,
                             const float* __restrict__ w1s,
                             float* __restrict__ y1) {
    int b = blockIdx.y, oy0 = blockIdx.x * 4;
    int tid = threadIdx.x;
    int c = tid & 63, xq = tid >> 6;

    __shared__ float xs[3][7][36];  // rows iy = oy0-1 .. oy0+5, col = ix+1
    __shared__ float2 sred[256];

    for (int i = tid; i < 3 * 7 * 36; i += 256) {
        int col = i % 36;
        int r   = (i / 36) % 7;
        int ci  = i / 252;
        int ix = col - 1, iy = oy0 - 1 + r;
        float v = 0.f;
        if (ix >= 0 && ix < 32 && iy >= 0 && iy < 32)
            v = x[(((size_t)b * 3 + ci) * 32 + iy) * 32 + ix];
        xs[ci][r][col] = v;
    }

    float wr[48];
#pragma unroll
    for (int k = 0; k < 48; k++) wr[k] = w1s[k * 64 + c];  // coalesced
    __syncthreads();

    float s1 = 0.f, s2 = 0.f;
#pragma unroll
    for (int r = 0; r < 4; r++) {
        float acc[8];
#pragma unroll
        for (int j = 0; j < 8; j++) acc[j] = 0.f;
#pragma unroll
        for (int ci = 0; ci < 3; ci++) {
#pragma unroll
            for (int kh = 0; kh < 4; kh++) {
                float rx[11];
#pragma unroll
                for (int t = 0; t < 11; t++) rx[t] = xs[ci][r + kh][xq * 8 + t];
#pragma unroll
                for (int kw = 0; kw < 4; kw++) {
                    float wv = wr[ci * 16 + kh * 4 + kw];
#pragma unroll
                    for (int j = 0; j < 8; j++) acc[j] += wv * rx[j + kw];
                }
            }
        }
        size_t obase = (((size_t)b * 32 + oy0 + r) * 32 + xq * 8) * 64 + c;
#pragma unroll
        for (int j = 0; j < 8; j++) {
            y1[obase + (size_t)j * 64] = acc[j];
            s1 += acc[j];
            s2 += acc[j] * acc[j];
        }
    }

    // reduce over xq (4 groups) -> g_part[slice][c]
    sred[tid] = make_float2(s1, s2);
    __syncthreads();
    if (tid < 64) {
        float2 a = sred[tid], b1 = sred[tid + 64], c1 = sred[tid + 128],
               d1 = sred[tid + 192];
        int slice = b * 8 + blockIdx.x;
        g_part[(slice * 64 + tid) * 2]     = a.x + b1.x + c1.x + d1.x;
        g_part[(slice * 64 + tid) * 2 + 1] = a.y + b1.y + c1.y + d1.y;
    }
}

// ---------------------------------------------------------------------------
// Reduce partials over slices + shift-BN finalize. One block per channel.
// ---------------------------------------------------------------------------
template <int C>
__global__ void reduce_finalize_kernel(const float* __restrict__ gamma,
                                       int nslices, int P) {
    int c = blockIdx.x;
    int tid = threadIdx.x;
    float s1 = 0.f, s2 = 0.f;
    for (int s = tid; s < nslices; s += 256) {
        s1 += g_part[(s * C + c) * 2];
        s2 += g_part[(s * C + c) * 2 + 1];
    }
    __shared__ double sd1[256], sd2[256];
    sd1[tid] = (double)s1;
    sd2[tid] = (double)s2;
    __syncthreads();
    for (int s = 128; s > 0; s >>= 1) {
        if (tid < s) {
            sd1[tid] += sd1[tid + s];
            sd2[tid] += sd2[tid + s];
        }
        __syncthreads();
    }
    if (tid == 0) {
        double mean = sd1[0] / (double)P;
        double var  = sd2[0] / (double)P - mean * mean;
        double inv  = (double)gamma[c] / sqrt(var + 1e-5);
        double sh   = rint(log2(fabs(inv) + 1e-12));
        if (sh > 4.0) sh = 4.0;
        if (sh < -4.0) sh = -4.0;
        double sgn = (inv > 0.0) ? 1.0 : ((inv < 0.0) ? -1.0 : 0.0);
        g_mean[c]  = (float)mean;
        g_scale[c] = (float)(sgn * exp2(sh));
    }
}

// ---------------------------------------------------------------------------
// BN apply + 2x2 maxpool + sign, 4 channels per thread (float4 / char4).
// BN applied before max (exact for negative scales).
// ---------------------------------------------------------------------------
__global__ void bn_pool_sign4_kernel(const float* __restrict__ y,
                                     int8_t* __restrict__ out,
                                     const float* __restrict__ beta,
                                     int H, int C, int total4) {
    int idx = blockIdx.x * 256 + threadIdx.x;
    if (idx >= total4) return;
    int e = idx * 4;
    int Ho = H >> 1;
    int c = e % C;
    int t = e / C;
    int ox = t % Ho; t /= Ho;
    int oy = t % Ho;
    int b  = t / Ho;
    float4 m  = *(const float4*)(g_mean + c);
    float4 s  = *(const float4*)(g_scale + c);
    float4 bt = *(const float4*)(beta + c);
    size_t base = (((size_t)b * H + 2 * oy) * H + 2 * ox) * C + c;
    float4 v0 = *(const float4*)(y + base);
    float4 v1 = *(const float4*)(y + base + C);
    float4 v2 = *(const float4*)(y + base + (size_t)H * C);
    float4 v3 = *(const float4*)(y + base + (size_t)H * C + C);
    float r0 = fmaxf(fmaxf((v0.x - m.x) * s.x, (v1.x - m.x) * s.x),
                     fmaxf((v2.x - m.x) * s.x, (v3.x - m.x) * s.x)) + bt.x;
    float r1 = fmaxf(fmaxf((v0.y - m.y) * s.y, (v1.y - m.y) * s.y),
                     fmaxf((v2.y - m.y) * s.y, (v3.y - m.y) * s.y)) + bt.y;
    float r2 = fmaxf(fmaxf((v0.z - m.z) * s.z, (v1.z - m.z) * s.z),
                     fmaxf((v2.z - m.z) * s.z, (v3.z - m.z) * s.z)) + bt.z;
    float r3 = fmaxf(fmaxf((v0.w - m.w) * s.w, (v1.w - m.w) * s.w),
                     fmaxf((v2.w - m.w) * s.w, (v3.w - m.w) * s.w)) + bt.w;
    char4 o;
    o.x = (char)((r0 > 0.f) ? 1 : ((r0 < 0.f) ? -1 : 0));
    o.y = (char)((r1 > 0.f) ? 1 : ((r1 < 0.f) ? -1 : 0));
    o.z = (char)((r2 > 0.f) ? 1 : ((r2 < 0.f) ? -1 : 0));
    o.w = (char)((r3 > 0.f) ? 1 : ((r3 < 0.f) ? -1 : 0));
    ((char4*)out)[idx] = o;
}

// BN apply + sign, 4 channels per thread
__global__ void bn_sign4_kernel(const float* __restrict__ y,
                                int8_t* __restrict__ out,
                                const float* __restrict__ beta,
                                int C, int total4) {
    int idx = blockIdx.x * 256 + threadIdx.x;
    if (idx >= total4) return;
    int c = (idx * 4) % C;
    float4 m  = *(const float4*)(g_mean + c);
    float4 s  = *(const float4*)(g_scale + c);
    float4 bt = *(const float4*)(beta + c);
    float4 v = ((const float4*)y)[idx];
    float r0 = (v.x - m.x) * s.x + bt.x;
    float r1 = (v.y - m.y) * s.y + bt.y;
    float r2 = (v.z - m.z) * s.z + bt.z;
    float r3 = (v.w - m.w) * s.w + bt.w;
    char4 o;
    o.x = (char)((r0 > 0.f) ? 1 : ((r0 < 0.f) ? -1 : 0));
    o.y = (char)((r1 > 0.f) ? 1 : ((r1 < 0.f) ? -1 : 0));
    o.z = (char)((r2 > 0.f) ? 1 : ((r2 < 0.f) ? -1 : 0));
    o.w = (char)((r3 > 0.f) ? 1 : ((r3 < 0.f) ? -1 : 0));
    ((char4*)out)[idx] = o;
}

// ---------------------------------------------------------------------------
// Grouped 4x4 binary conv, fused stats.
// ---------------------------------------------------------------------------
template <int H, int C>
__global__ void conv_grp_kernel(const int8_t* __restrict__ a,
                                const float* __restrict__ w,
                                float* __restrict__ out) {
    int b = blockIdx.y, oy = blockIdx.x;
    int tid = threadIdx.x;
    constexpr int PW = H + 3;
    __shared__ __align__(16) int8_t as[4][PW][C];
    __shared__ float2 sred[256];

    const int8_t* abase = a + (size_t)b * H * H * C;
    int total4 = (4 * PW * C) / 4;
    for (int i = tid; i < total4; i += 256) {
        int e = i * 4;
        int cc = e % C;
        int col = (e / C) % PW;
        int r = e / (C * PW);
        int ix = col - 1, iy = oy - 1 + r;
        int v = 0;
        if (ix >= 0 && ix < H && iy >= 0 && iy < H)
            v = *(const int*)(abase + ((size_t)iy * H + ix) * C + cc);
        *(int*)(&as[r][col][cc]) = v;
    }

    int c = tid % C;
    int xq = tid / C;
    int g2 = c & ~1;
    int wsgn[32];
    const float* wc = w + (size_t)c * 32;
#pragma unroll
    for (int k = 0; k < 32; k++) {
        float wv = wc[k];
        wsgn[k] = (wv > 0.f) - (wv < 0.f);
    }
    __syncthreads();

    float s1 = 0.f, s2 = 0.f;
    constexpr int SPAN = (H * C) / 256;
    for (int j = 0; j < SPAN; j++) {
        int ox = xq * SPAN + j;
        int acc = 0;
#pragma unroll
        for (int l = 0; l < 2; l++)
#pragma unroll
            for (int kh = 0; kh < 4; kh++)
#pragma unroll
                for (int kw = 0; kw < 4; kw++)
                    acc += wsgn[l * 16 + kh * 4 + kw] * (int)as[kh][ox + kw][g2 + l];
        float f = (float)acc;
        out[(((size_t)b * H + oy) * H + ox) * C + c] = f;
        s1 += f;
        s2 += f * f;
    }

    int slice = b * gridDim.x + blockIdx.x;
    if (C == 256) {
        g_part[(slice * 256 + c) * 2]     = s1;
        g_part[(slice * 256 + c) * 2 + 1] = s2;
    } else {
        sred[tid] = make_float2(s1, s2);
        __syncthreads();
        if (tid < C) {
            float a1 = 0.f, a2 = 0.f;
            for (int q = 0; q < 256 / C; q++) {
                a1 += sred[q * C + tid].x;
                a2 += sred[q * C + tid].y;
            }
            g_part[(slice * C + tid) * 2]     = a1;
            g_part[(slice * C + tid) * 2 + 1] = a2;
        }
    }
}

// pack sign of weights into int8
__global__ void pack_sign_kernel(const float* __restrict__ w,
                                 int8_t* __restrict__ dst, int n) {
    int i = blockIdx.x * 256 + threadIdx.x;
    if (i >= n) return;
    float v = w[i];
    dst[i] = (int8_t)((v > 0.f) ? 1 : ((v < 0.f) ? -1 : 0));
}

// ---------------------------------------------------------------------------
// 1x1 binary conv as GEMM with dp4a, fused per-thread stats.
// ---------------------------------------------------------------------------
__global__ void gemm64_kernel(const int8_t* __restrict__ a,
                              const int8_t* __restrict__ wp,
                              float* __restrict__ out) {
    __shared__ __align__(16) int as[128][16];
    int c = threadIdx.x;
    int wr[16];
    const int* w4 = (const int*)wp + c * 16;
#pragma unroll
    for (int k = 0; k < 16; k++) wr[k] = w4[k];
    size_t p0 = (size_t)blockIdx.x * 128;
    const int* a4 = (const int*)(a + p0 * 64);
    for (int i = threadIdx.x; i < 2048; i += 256) as[i >> 4][i & 15] = a4[i];
    __syncthreads();
    float s1 = 0.f, s2 = 0.f;
    for (int p = 0; p < 128; p++) {
        int acc = 0;
        const int4* av = (const int4*)as[p];
#pragma unroll
        for (int k4 = 0; k4 < 4; k4++) {
            int4 v = av[k4];
            acc = __dp4a(v.x, wr[k4 * 4 + 0], acc);
            acc = __dp4a(v.y, wr[k4 * 4 + 1], acc);
            acc = __dp4a(v.z, wr[k4 * 4 + 2], acc);
            acc = __dp4a(v.w, wr[k4 * 4 + 3], acc);
        }
        float f = (float)acc;
        out[(p0 + p) * 256 + c] = f;
        s1 += f;
        s2 += f * f;
    }
    g_part[(blockIdx.x * 256 + c) * 2]     = s1;
    g_part[(blockIdx.x * 256 + c) * 2 + 1] = s2;
}

__global__ void gemm256_kernel(const int8_t* __restrict__ a,
                               const int8_t* __restrict__ wp,
                               float* __restrict__ out) {
    __shared__ __align__(16) int as[64][64];
    int c = threadIdx.x;
    int wr[64];
    const int* w4 = (const int*)wp + c * 64;
#pragma unroll
    for (int k = 0; k < 64; k++) wr[k] = w4[k];
    size_t p0 = (size_t)blockIdx.x * 64;
    const int* a4 = (const int*)(a + p0 * 256);
    for (int i = threadIdx.x; i < 4096; i += 256) as[i >> 6][i & 63] = a4[i];
    __syncthreads();
    float s1 = 0.f, s2 = 0.f;
    for (int p = 0; p < 64; p++) {
        int acc = 0;
        const int4* av = (const int4*)as[p];
#pragma unroll
        for (int k4 = 0; k4 < 16; k4++) {
            int4 v = av[k4];
            acc = __dp4a(v.x, wr[k4 * 4 + 0], acc);
            acc = __dp4a(v.y, wr[k4 * 4 + 1], acc);
            acc = __dp4a(v.z, wr[k4 * 4 + 2], acc);
            acc = __dp4a(v.w, wr[k4 * 4 + 3], acc);
        }
        float f = (float)acc;
        out[(p0 + p) * 256 + c] = f;
        s1 += f;
        s2 += f * f;
    }
    g_part[(blockIdx.x * 256 + c) * 2]     = s1;
    g_part[(blockIdx.x * 256 + c) * 2 + 1] = s2;
}

// ---------------------------------------------------------------------------
// FC: fc_w to n-major over NHWC-flatten index; 4 batches per block.
// ---------------------------------------------------------------------------
__global__ void fcw_reorder_kernel(const float* __restrict__ fcw,
                                   float* __restrict__ fcwr) {
    int i = blockIdx.x * 256 + threadIdx.x;  // i = n*16384 + e, e = hw*256 + c
    if (i >= 16384 * 10) return;
    int n = i / 16384;
    int e = i % 16384;
    int c = e & 255, hw = e >> 8;
    fcwr[i] = fcw[n * 16384 + c * 64 + hw];
}

#define FCB 4
__global__ void fc_kernel(const float* __restrict__ y5,
                          const float* __restrict__ fcwr,
                          const float* __restrict__ fc_b,
                          const float* __restrict__ beta,
                          float* __restrict__ out) {
    int b0 = blockIdx.x * FCB;
    int tid = threadIdx.x;
    float acc[FCB][10];
#pragma unroll
    for (int bb = 0; bb < FCB; bb++)
#pragma unroll
        for (int n = 0; n < 10; n++) acc[bb][n] = 0.f;

    for (int i = tid; i < 16384; i += 256) {
        int c = i & 255;
        float m = g_mean[c], s = g_scale[c], bt = beta[c];
        float w[10];
#pragma unroll
        for (int n = 0; n < 10; n++) w[n] = fcwr[n * 16384 + i];
#pragma unroll
        for (int bb = 0; bb < FCB; bb++) {
            float v = (y5[(size_t)(b0 + bb) * 16384 + i] - m) * s + bt;
#pragma unroll
            for (int n = 0; n < 10; n++) acc[bb][n] += v * w[n];
        }
    }

    __shared__ float sred[8][FCB * 10];
    int lane = tid & 31, wid = tid >> 5;
#pragma unroll
    for (int bb = 0; bb < FCB; bb++)
#pragma unroll
        for (int n = 0; n < 10; n++) {
            float v = acc[bb][n];
#pragma unroll
            for (int o = 16; o > 0; o >>= 1)
                v += __shfl_xor_sync(0xffffffffu, v, o);
            if (lane == 0) sred[wid][bb * 10 + n] = v;
        }
    __syncthreads();
    if (tid < FCB * 10) {
        float v = 0.f;
#pragma unroll
        for (int w8 = 0; w8 < 8; w8++) v += sred[w8][tid];
        int bb = tid / 10, n = tid % 10;
        out[(b0 + bb) * 10 + n] = v + fc_b[n];
    }
}

// ---------------------------------------------------------------------------
extern "C" void kernel_launch(void* const* d_in, const int* in_sizes, int n_in,
                              void* d_out, int out_size) {
    const float* x    = (const float*)d_in[0];
    const float* w1   = (const float*)d_in[1];
    const float* g1   = (const float*)d_in[2];
    const float* b1   = (const float*)d_in[3];
    const float* w2_1 = (const float*)d_in[4];
    const float* g2_1 = (const float*)d_in[5];
    const float* b2_1 = (const float*)d_in[6];
    const float* w2_2 = (const float*)d_in[7];
    const float* g2_2 = (const float*)d_in[8];
    const float* b2_2 = (const float*)d_in[9];
    const float* w3_1 = (const float*)d_in[10];
    const float* g3_1 = (const float*)d_in[11];
    const float* b3_1 = (const float*)d_in[12];
    const float* w3_2 = (const float*)d_in[13];
    const float* g3_2 = (const float*)d_in[14];
    const float* b3_2 = (const float*)d_in[15];
    const float* fcw  = (const float*)d_in[16];
    const float* fcb  = (const float*)d_in[17];
    float* out = (float*)d_out;

    float *y1, *y2, *y3, *y4, *y5, *fcwr, *w1s;
    int8_t *a1, *a2, *a3, *a4, *wp2, *wp3;
    cudaGetSymbolAddress((void**)&y1, g_y1);
    cudaGetSymbolAddress((void**)&y2, g_y2);
    cudaGetSymbolAddress((void**)&y3, g_y3);
    cudaGetSymbolAddress((void**)&y4, g_y4);
    cudaGetSymbolAddress((void**)&y5, g_y5);
    cudaGetSymbolAddress((void**)&a1, g_a1);
    cudaGetSymbolAddress((void**)&a2, g_a2);
    cudaGetSymbolAddress((void**)&a3, g_a3);
    cudaGetSymbolAddress((void**)&a4, g_a4);
    cudaGetSymbolAddress((void**)&wp2, g_wp2);
    cudaGetSymbolAddress((void**)&wp3, g_wp3);
    cudaGetSymbolAddress((void**)&fcwr, g_fcwr);
    cudaGetSymbolAddress((void**)&w1s, g_w1s);

    // weight prep (independent of activations)
    pack_w1_kernel<<<12, 256>>>(w1, w1s);
    pack_sign_kernel<<<64, 256>>>(w2_2, wp2, 256 * 64);
    pack_sign_kernel<<<256, 256>>>(w3_2, wp3, 256 * 256);
    fcw_reorder_kernel<<<640, 256>>>(fcw, fcwr);

    // Stage 1: conv1 (+stats) -> finalize -> bn+pool+sign
    conv1_kernel<<<dim3(8, BATCH), 256>>>(x, w1s, y1);
    reduce_finalize_kernel<64><<<64, 256>>>(g1, 512 * 8, 512 * 1024);
    bn_pool_sign4_kernel<<<(512 * 256 * 64 / 4 + 255) / 256, 256>>>(
        y1, a1, b1, 32, 64, 512 * 256 * 64 / 4);

    // Stage 2
    conv_grp_kernel<16, 64><<<dim3(16, BATCH), 256>>>(a1, w2_1, y2);
    reduce_finalize_kernel<64><<<64, 256>>>(g2_1, 512 * 16, 512 * 256);
    bn_sign4_kernel<<<(512 * 256 * 64 / 4 + 255) / 256, 256>>>(
        y2, a2, b2_1, 64, 512 * 256 * 64 / 4);

    gemm64_kernel<<<(512 * 256) / 128, 256>>>(a2, wp2, y3);
    reduce_finalize_kernel<256><<<256, 256>>>(g2_2, 1024, 512 * 256);
    bn_pool_sign4_kernel<<<(512 * 64 * 256 / 4 + 255) / 256, 256>>>(
        y3, a3, b2_2, 16, 256, 512 * 64 * 256 / 4);

    // Stage 3
    conv_grp_kernel<8, 256><<<dim3(8, BATCH), 256>>>(a3, w3_1, y4);
    reduce_finalize_kernel<256><<<256, 256>>>(g3_1, 512 * 8, 512 * 64);
    bn_sign4_kernel<<<(512 * 64 * 256 / 4 + 255) / 256, 256>>>(
        y4, a4, b3_1, 256, 512 * 64 * 256 / 4);

    gemm256_kernel<<<(512 * 64) / 64, 256>>>(a4, wp3, y5);
    reduce_finalize_kernel<256><<<256, 256>>>(g3_2, 512, 512 * 64);

    // FC (bn3_2 fused)
    fc_kernel<<<BATCH / FCB, 256>>>(y5, fcwr, fcb, b3_2, out);
}

// round 5
// speedup vs baseline: 3.3289x; 1.7830x over previous
#include <cuda_runtime.h>
#include <cstdint>
#include <cstdio>

// ---------------------------------------------------------------------------
// LiBNet forward, batch 512.  Round 5: int8/int16 intermediates (exact),
// transposed+coalesced weight packs for grouped convs, transposed stats
// partials, templated BN kernels.
// ---------------------------------------------------------------------------

#define BATCH 512

// Scratch (device globals)
__device__ float   g_y1[512u*1024u*64u];   // conv1 out  [b,32,32,64] fp32
__device__ int8_t  g_a1[512u*256u*64u];    // sign(pool(bn1)) [b,16,16,64]
__device__ int8_t  g_y2b[512u*256u*64u];   // conv2_1 out int8 (|v|<=32)
__device__ int8_t  g_a2[512u*256u*64u];    // sign(bn2_1)
__device__ int8_t  g_y3b[512u*256u*256u];  // conv2_2 out int8 (|v|<=64)
__device__ int8_t  g_a3[512u*64u*256u];    // sign(pool(bn2_2)) [b,8,8,256]
__device__ int8_t  g_y4b[512u*64u*256u];   // conv3_1 out int8 (|v|<=32)
__device__ int8_t  g_a4[512u*64u*256u];    // sign(bn3_1)
__device__ int16_t g_y5s[512u*64u*256u];   // conv3_2 out int16 (|v|<=256)
__device__ float   g_w1s[48*64];           // sign(w1) transposed [k][c]
__device__ int8_t  g_wg2[32*64];           // sign(w2_1) transposed [k][c]
__device__ int8_t  g_wg3[32*256];          // sign(w3_1) transposed [k][c]
__device__ int8_t  g_wp2[256*64];          // sign(w2_2)
__device__ int8_t  g_wp3[256*256];         // sign(w3_2)
__device__ float   g_part[2097152];        // stats partials [c][slice] (+C off for sq)
__device__ float   g_mean[256];
__device__ float   g_scale[256];
__device__ float   g_fcwr[16384*10];       // fc_w n-major over NHWC-flatten

// ---------------------------------------------------------------------------
// weight prep
// ---------------------------------------------------------------------------
__global__ void pack_w1_kernel(const float* __restrict__ w1,
                               float* __restrict__ w1s) {
    int i = blockIdx.x * 256 + threadIdx.x;  // i = k*64 + c
    if (i >= 48 * 64) return;
    int c = i & 63, k = i >> 6;
    float v = w1[c * 48 + k];
    w1s[i] = (v > 0.f) ? 1.f : ((v < 0.f) ? -1.f : 0.f);
}

// grouped-conv weights [C,2,4,4] -> int8 transposed [k=32][c=C]
__global__ void pack_grp_kernel(const float* __restrict__ w,
                                int8_t* __restrict__ dst, int C) {
    int i = blockIdx.x * 256 + threadIdx.x;  // i = k*C + c
    if (i >= 32 * C) return;
    int c = i % C, k = i / C;
    float v = w[c * 32 + k];
    dst[i] = (int8_t)((v > 0.f) ? 1 : ((v < 0.f) ? -1 : 0));
}

__global__ void pack_sign_kernel(const float* __restrict__ w,
                                 int8_t* __restrict__ dst, int n) {
    int i = blockIdx.x * 256 + threadIdx.x;
    if (i >= n) return;
    float v = w[i];
    dst[i] = (int8_t)((v > 0.f) ? 1 : ((v < 0.f) ? -1 : 0));
}

__global__ void fcw_reorder_kernel(const float* __restrict__ fcw,
                                   float* __restrict__ fcwr) {
    int i = blockIdx.x * 256 + threadIdx.x;  // i = n*16384 + e, e = hw*256 + c
    if (i >= 16384 * 10) return;
    int n = i / 16384;
    int e = i % 16384;
    int c = e & 255, hw = e >> 8;
    fcwr[i] = fcw[n * 16384 + c * 64 + hw];
}

// ---------------------------------------------------------------------------
// conv1: x [b,3,32,32] NCHW, pad (t1,b2,l1,r2), out NHWC [b,32,32,64] fp32.
// 4 output rows per block; fused channel stats -> g_part [c][slice].
// ---------------------------------------------------------------------------
__global__ void conv1_kernel(const float* __restrict__ x,
                             const float* __restrict__ w1s,
                             float* __restrict__ y1) {
    const int NS = 4096;  // 8 * 512 slices
    int b = blockIdx.y, oy0 = blockIdx.x * 4;
    int tid = threadIdx.x;
    int c = tid & 63, xq = tid >> 6;

    __shared__ float xs[3][7][36];
    __shared__ float2 sred[256];

    for (int i = tid; i < 3 * 7 * 36; i += 256) {
        int col = i % 36;
        int r   = (i / 36) % 7;
        int ci  = i / 252;
        int ix = col - 1, iy = oy0 - 1 + r;
        float v = 0.f;
        if (ix >= 0 && ix < 32 && iy >= 0 && iy < 32)
            v = x[(((size_t)b * 3 + ci) * 32 + iy) * 32 + ix];
        xs[ci][r][col] = v;
    }

    float wr[48];
#pragma unroll
    for (int k = 0; k < 48; k++) wr[k] = w1s[k * 64 + c];
    __syncthreads();

    float s1 = 0.f, s2 = 0.f;
#pragma unroll
    for (int r = 0; r < 4; r++) {
        float acc[8];
#pragma unroll
        for (int j = 0; j < 8; j++) acc[j] = 0.f;
#pragma unroll
        for (int ci = 0; ci < 3; ci++) {
#pragma unroll
            for (int kh = 0; kh < 4; kh++) {
                float rx[11];
#pragma unroll
                for (int t = 0; t < 11; t++) rx[t] = xs[ci][r + kh][xq * 8 + t];
#pragma unroll
                for (int kw = 0; kw < 4; kw++) {
                    float wv = wr[ci * 16 + kh * 4 + kw];
#pragma unroll
                    for (int j = 0; j < 8; j++) acc[j] += wv * rx[j + kw];
                }
            }
        }
        size_t obase = (((size_t)b * 32 + oy0 + r) * 32 + xq * 8) * 64 + c;
#pragma unroll
        for (int j = 0; j < 8; j++) {
            y1[obase + (size_t)j * 64] = acc[j];
            s1 += acc[j];
            s2 += acc[j] * acc[j];
        }
    }

    sred[tid] = make_float2(s1, s2);
    __syncthreads();
    if (tid < 64) {
        float2 a = sred[tid], b1 = sred[tid + 64], c1 = sred[tid + 128],
               d1 = sred[tid + 192];
        int slice = b * 8 + blockIdx.x;
        g_part[tid * NS + slice]        = a.x + b1.x + c1.x + d1.x;
        g_part[(64 + tid) * NS + slice] = a.y + b1.y + c1.y + d1.y;
    }
}

// ---------------------------------------------------------------------------
// Reduce partials (coalesced: [c][slice]) + shift-BN finalize.
// ---------------------------------------------------------------------------
template <int C>
__global__ void reduce_finalize_kernel(const float* __restrict__ gamma,
                                       int nslices, int P) {
    int c = blockIdx.x;
    int tid = threadIdx.x;
    float s1 = 0.f, s2 = 0.f;
    const float* p1 = g_part + (size_t)c * nslices;
    const float* p2 = g_part + (size_t)(C + c) * nslices;
#pragma unroll 4
    for (int s = tid; s < nslices; s += 256) {
        s1 += p1[s];
        s2 += p2[s];
    }
    __shared__ double sd1[256], sd2[256];
    sd1[tid] = (double)s1;
    sd2[tid] = (double)s2;
    __syncthreads();
    for (int s = 128; s > 0; s >>= 1) {
        if (tid < s) {
            sd1[tid] += sd1[tid + s];
            sd2[tid] += sd2[tid + s];
        }
        __syncthreads();
    }
    if (tid == 0) {
        double mean = sd1[0] / (double)P;
        double var  = sd2[0] / (double)P - mean * mean;
        double inv  = (double)gamma[c] / sqrt(var + 1e-5);
        double sh   = rint(log2(fabs(inv) + 1e-12));
        if (sh > 4.0) sh = 4.0;
        if (sh < -4.0) sh = -4.0;
        double sgn = (inv > 0.0) ? 1.0 : ((inv < 0.0) ? -1.0 : 0.0);
        g_mean[c]  = (float)mean;
        g_scale[c] = (float)(sgn * exp2(sh));
    }
}

// ---------------------------------------------------------------------------
// BN + 2x2 maxpool + sign, fp32 input (stage 1). 4 ch/thread.
// ---------------------------------------------------------------------------
template <int H, int C>
__global__ void bn_pool_sign4_f_kernel(const float* __restrict__ y,
                                       int8_t* __restrict__ out,
                                       const float* __restrict__ beta,
                                       int total4) {
    int idx = blockIdx.x * 256 + threadIdx.x;
    if (idx >= total4) return;
    constexpr int Ho = H / 2;
    int e = idx * 4;
    int c = e % C;
    int t = e / C;
    int ox = t % Ho; t /= Ho;
    int oy = t % Ho;
    int b  = t / Ho;
    float4 m  = *(const float4*)(g_mean + c);
    float4 s  = *(const float4*)(g_scale + c);
    float4 bt = *(const float4*)(beta + c);
    size_t base = (((size_t)b * H + 2 * oy) * H + 2 * ox) * C + c;
    float4 v0 = *(const float4*)(y + base);
    float4 v1 = *(const float4*)(y + base + C);
    float4 v2 = *(const float4*)(y + base + (size_t)H * C);
    float4 v3 = *(const float4*)(y + base + (size_t)H * C + C);
    float r0 = fmaxf(fmaxf((v0.x - m.x) * s.x, (v1.x - m.x) * s.x),
                     fmaxf((v2.x - m.x) * s.x, (v3.x - m.x) * s.x)) + bt.x;
    float r1 = fmaxf(fmaxf((v0.y - m.y) * s.y, (v1.y - m.y) * s.y),
                     fmaxf((v2.y - m.y) * s.y, (v3.y - m.y) * s.y)) + bt.y;
    float r2 = fmaxf(fmaxf((v0.z - m.z) * s.z, (v1.z - m.z) * s.z),
                     fmaxf((v2.z - m.z) * s.z, (v3.z - m.z) * s.z)) + bt.z;
    float r3 = fmaxf(fmaxf((v0.w - m.w) * s.w, (v1.w - m.w) * s.w),
                     fmaxf((v2.w - m.w) * s.w, (v3.w - m.w) * s.w)) + bt.w;
    char4 o;
    o.x = (char)((r0 > 0.f) ? 1 : ((r0 < 0.f) ? -1 : 0));
    o.y = (char)((r1 > 0.f) ? 1 : ((r1 < 0.f) ? -1 : 0));
    o.z = (char)((r2 > 0.f) ? 1 : ((r2 < 0.f) ? -1 : 0));
    o.w = (char)((r3 > 0.f) ? 1 : ((r3 < 0.f) ? -1 : 0));
    ((char4*)out)[idx] = o;
}

// BN + 2x2 maxpool + sign, int8 input (stage 2->3). 4 ch/thread.
template <int H, int C>
__global__ void bn_pool_sign4_i8_kernel(const int8_t* __restrict__ y,
                                        int8_t* __restrict__ out,
                                        const float* __restrict__ beta,
                                        int total4) {
    int idx = blockIdx.x * 256 + threadIdx.x;
    if (idx >= total4) return;
    constexpr int Ho = H / 2;
    int e = idx * 4;
    int c = e % C;
    int t = e / C;
    int ox = t % Ho; t /= Ho;
    int oy = t % Ho;
    int b  = t / Ho;
    float4 m  = *(const float4*)(g_mean + c);
    float4 s  = *(const float4*)(g_scale + c);
    float4 bt = *(const float4*)(beta + c);
    size_t base = (((size_t)b * H + 2 * oy) * H + 2 * ox) * C + c;
    char4 u0 = *(const char4*)(y + base);
    char4 u1 = *(const char4*)(y + base + C);
    char4 u2 = *(const char4*)(y + base + (size_t)H * C);
    char4 u3 = *(const char4*)(y + base + (size_t)H * C + C);
    float r0 = fmaxf(fmaxf(((float)u0.x - m.x) * s.x, ((float)u1.x - m.x) * s.x),
                     fmaxf(((float)u2.x - m.x) * s.x, ((float)u3.x - m.x) * s.x)) + bt.x;
    float r1 = fmaxf(fmaxf(((float)u0.y - m.y) * s.y, ((float)u1.y - m.y) * s.y),
                     fmaxf(((float)u2.y - m.y) * s.y, ((float)u3.y - m.y) * s.y)) + bt.y;
    float r2 = fmaxf(fmaxf(((float)u0.z - m.z) * s.z, ((float)u1.z - m.z) * s.z),
                     fmaxf(((float)u2.z - m.z) * s.z, ((float)u3.z - m.z) * s.z)) + bt.z;
    float r3 = fmaxf(fmaxf(((float)u0.w - m.w) * s.w, ((float)u1.w - m.w) * s.w),
                     fmaxf(((float)u2.w - m.w) * s.w, ((float)u3.w - m.w) * s.w)) + bt.w;
    char4 o;
    o.x = (char)((r0 > 0.f) ? 1 : ((r0 < 0.f) ? -1 : 0));
    o.y = (char)((r1 > 0.f) ? 1 : ((r1 < 0.f) ? -1 : 0));
    o.z = (char)((r2 > 0.f) ? 1 : ((r2 < 0.f) ? -1 : 0));
    o.w = (char)((r3 > 0.f) ? 1 : ((r3 < 0.f) ? -1 : 0));
    ((char4*)out)[idx] = o;
}

// BN + sign, int8 input, elementwise. 4 ch/thread.
template <int C>
__global__ void bn_sign4_i8_kernel(const int8_t* __restrict__ y,
                                   int8_t* __restrict__ out,
                                   const float* __restrict__ beta,
                                   int total4) {
    int idx = blockIdx.x * 256 + threadIdx.x;
    if (idx >= total4) return;
    int c = (idx * 4) % C;
    float4 m  = *(const float4*)(g_mean + c);
    float4 s  = *(const float4*)(g_scale + c);
    float4 bt = *(const float4*)(beta + c);
    char4 u = ((const char4*)y)[idx];
    float r0 = ((float)u.x - m.x) * s.x + bt.x;
    float r1 = ((float)u.y - m.y) * s.y + bt.y;
    float r2 = ((float)u.z - m.z) * s.z + bt.z;
    float r3 = ((float)u.w - m.w) * s.w + bt.w;
    char4 o;
    o.x = (char)((r0 > 0.f) ? 1 : ((r0 < 0.f) ? -1 : 0));
    o.y = (char)((r1 > 0.f) ? 1 : ((r1 < 0.f) ? -1 : 0));
    o.z = (char)((r2 > 0.f) ? 1 : ((r2 < 0.f) ? -1 : 0));
    o.w = (char)((r3 > 0.f) ? 1 : ((r3 < 0.f) ? -1 : 0));
    ((char4*)out)[idx] = o;
}

// ---------------------------------------------------------------------------
// Grouped 4x4 binary conv, int8 out, int stats, coalesced weight pack.
// ---------------------------------------------------------------------------
template <int H, int C>
__global__ void conv_grp_kernel(const int8_t* __restrict__ a,
                                const int8_t* __restrict__ wg,
                                int8_t* __restrict__ out, int NS) {
    int b = blockIdx.y, oy = blockIdx.x;
    int tid = threadIdx.x;
    constexpr int PW = H + 3;
    __shared__ __align__(16) int8_t as[4][PW][C];
    __shared__ int2 sred[256];

    const int8_t* abase = a + (size_t)b * H * H * C;
    int total4 = (4 * PW * C) / 4;
    for (int i = tid; i < total4; i += 256) {
        int e = i * 4;
        int cc = e % C;
        int col = (e / C) % PW;
        int r = e / (C * PW);
        int ix = col - 1, iy = oy - 1 + r;
        int v = 0;
        if (ix >= 0 && ix < H && iy >= 0 && iy < H)
            v = *(const int*)(abase + ((size_t)iy * H + ix) * C + cc);
        *(int*)(&as[r][col][cc]) = v;
    }

    int c = tid % C;
    int xq = tid / C;
    int g2 = c & ~1;
    int wsgn[32];
#pragma unroll
    for (int k = 0; k < 32; k++) wsgn[k] = (int)wg[k * C + c];  // coalesced
    __syncthreads();

    int is1 = 0, is2 = 0;
    constexpr int SPAN = (H * C) / 256;
    for (int j = 0; j < SPAN; j++) {
        int ox = xq * SPAN + j;
        int acc = 0;
#pragma unroll
        for (int l = 0; l < 2; l++)
#pragma unroll
            for (int kh = 0; kh < 4; kh++)
#pragma unroll
                for (int kw = 0; kw < 4; kw++)
                    acc += wsgn[l * 16 + kh * 4 + kw] * (int)as[kh][ox + kw][g2 + l];
        out[(((size_t)b * H + oy) * H + ox) * C + c] = (int8_t)acc;
        is1 += acc;
        is2 += acc * acc;
    }

    int slice = b * gridDim.x + blockIdx.x;
    if (C == 256) {
        g_part[(size_t)c * NS + slice]       = (float)is1;
        g_part[(size_t)(C + c) * NS + slice] = (float)is2;
    } else {
        sred[tid] = make_int2(is1, is2);
        __syncthreads();
        if (tid < C) {
            int a1 = 0, a2 = 0;
            for (int q = 0; q < 256 / C; q++) {
                a1 += sred[q * C + tid].x;
                a2 += sred[q * C + tid].y;
            }
            g_part[(size_t)tid * NS + slice]       = (float)a1;
            g_part[(size_t)(C + tid) * NS + slice] = (float)a2;
        }
    }
}

// ---------------------------------------------------------------------------
// 1x1 binary conv as dp4a GEMM, int8/int16 out, int stats.
// ---------------------------------------------------------------------------
__global__ void gemm64_kernel(const int8_t* __restrict__ a,
                              const int8_t* __restrict__ wp,
                              int8_t* __restrict__ out) {
    const int NS = 1024;
    __shared__ __align__(16) int as[128][16];
    int c = threadIdx.x;
    int wr[16];
    const int* w4 = (const int*)wp + c * 16;
#pragma unroll
    for (int k = 0; k < 16; k++) wr[k] = w4[k];
    size_t p0 = (size_t)blockIdx.x * 128;
    const int* a4 = (const int*)(a + p0 * 64);
    for (int i = threadIdx.x; i < 2048; i += 256) as[i >> 4][i & 15] = a4[i];
    __syncthreads();
    int is1 = 0, is2 = 0;
    for (int p = 0; p < 128; p++) {
        int acc = 0;
        const int4* av = (const int4*)as[p];
#pragma unroll
        for (int k4 = 0; k4 < 4; k4++) {
            int4 v = av[k4];
            acc = __dp4a(v.x, wr[k4 * 4 + 0], acc);
            acc = __dp4a(v.y, wr[k4 * 4 + 1], acc);
            acc = __dp4a(v.z, wr[k4 * 4 + 2], acc);
            acc = __dp4a(v.w, wr[k4 * 4 + 3], acc);
        }
        out[(p0 + p) * 256 + c] = (int8_t)acc;
        is1 += acc;
        is2 += acc * acc;
    }
    g_part[(size_t)c * NS + blockIdx.x]         = (float)is1;
    g_part[(size_t)(256 + c) * NS + blockIdx.x] = (float)is2;
}

__global__ void gemm256_kernel(const int8_t* __restrict__ a,
                               const int8_t* __restrict__ wp,
                               int16_t* __restrict__ out) {
    const int NS = 512;
    __shared__ __align__(16) int as[64][64];
    int c = threadIdx.x;
    int wr[64];
    const int* w4 = (const int*)wp + c * 64;
#pragma unroll
    for (int k = 0; k < 64; k++) wr[k] = w4[k];
    size_t p0 = (size_t)blockIdx.x * 64;
    const int* a4 = (const int*)(a + p0 * 256);
    for (int i = threadIdx.x; i < 4096; i += 256) as[i >> 6][i & 63] = a4[i];
    __syncthreads();
    int is1 = 0, is2 = 0;
    for (int p = 0; p < 64; p++) {
        int acc = 0;
        const int4* av = (const int4*)as[p];
#pragma unroll
        for (int k4 = 0; k4 < 16; k4++) {
            int4 v = av[k4];
            acc = __dp4a(v.x, wr[k4 * 4 + 0], acc);
            acc = __dp4a(v.y, wr[k4 * 4 + 1], acc);
            acc = __dp4a(v.z, wr[k4 * 4 + 2], acc);
            acc = __dp4a(v.w, wr[k4 * 4 + 3], acc);
        }
        out[(p0 + p) * 256 + c] = (int16_t)acc;
        is1 += acc;
        is2 += acc * acc;
    }
    g_part[(size_t)c * NS + blockIdx.x]         = (float)is1;
    g_part[(size_t)(256 + c) * NS + blockIdx.x] = (float)is2;
}

// ---------------------------------------------------------------------------
// FC with fused bn3_2; 4 batches per block; int16 input.
// ---------------------------------------------------------------------------
#define FCB 4
__global__ void fc_kernel(const int16_t* __restrict__ y5,
                          const float* __restrict__ fcwr,
                          const float* __restrict__ fc_b,
                          const float* __restrict__ beta,
                          float* __restrict__ out) {
    int b0 = blockIdx.x * FCB;
    int tid = threadIdx.x;
    float acc[FCB][10];
#pragma unroll
    for (int bb = 0; bb < FCB; bb++)
#pragma unroll
        for (int n = 0; n < 10; n++) acc[bb][n] = 0.f;

    for (int i = tid; i < 16384; i += 256) {
        int c = i & 255;
        float m = g_mean[c], s = g_scale[c], bt = beta[c];
        float w[10];
#pragma unroll
        for (int n = 0; n < 10; n++) w[n] = fcwr[n * 16384 + i];
#pragma unroll
        for (int bb = 0; bb < FCB; bb++) {
            float v = ((float)y5[(size_t)(b0 + bb) * 16384 + i] - m) * s + bt;
#pragma unroll
            for (int n = 0; n < 10; n++) acc[bb][n] += v * w[n];
        }
    }

    __shared__ float sred[8][FCB * 10];
    int lane = tid & 31, wid = tid >> 5;
#pragma unroll
    for (int bb = 0; bb < FCB; bb++)
#pragma unroll
        for (int n = 0; n < 10; n++) {
            float v = acc[bb][n];
#pragma unroll
            for (int o = 16; o > 0; o >>= 1)
                v += __shfl_xor_sync(0xffffffffu, v, o);
            if (lane == 0) sred[wid][bb * 10 + n] = v;
        }
    __syncthreads();
    if (tid < FCB * 10) {
        float v = 0.f;
#pragma unroll
        for (int w8 = 0; w8 < 8; w8++) v += sred[w8][tid];
        int bb = tid / 10, n = tid % 10;
        out[(b0 + bb) * 10 + n] = v + fc_b[n];
    }
}

// ---------------------------------------------------------------------------
extern "C" void kernel_launch(void* const* d_in, const int* in_sizes, int n_in,
                              void* d_out, int out_size) {
    const float* x    = (const float*)d_in[0];
    const float* w1   = (const float*)d_in[1];
    const float* g1   = (const float*)d_in[2];
    const float* b1   = (const float*)d_in[3];
    const float* w2_1 = (const float*)d_in[4];
    const float* g2_1 = (const float*)d_in[5];
    const float* b2_1 = (const float*)d_in[6];
    const float* w2_2 = (const float*)d_in[7];
    const float* g2_2 = (const float*)d_in[8];
    const float* b2_2 = (const float*)d_in[9];
    const float* w3_1 = (const float*)d_in[10];
    const float* g3_1 = (const float*)d_in[11];
    const float* b3_1 = (const float*)d_in[12];
    const float* w3_2 = (const float*)d_in[13];
    const float* g3_2 = (const float*)d_in[14];
    const float* b3_2 = (const float*)d_in[15];
    const float* fcw  = (const float*)d_in[16];
    const float* fcb  = (const float*)d_in[17];
    float* out = (float*)d_out;

    float *y1, *fcwr, *w1s;
    int8_t *a1, *a2, *a3, *a4, *y2b, *y3b, *y4b, *wp2, *wp3, *wg2, *wg3;
    int16_t *y5s;
    cudaGetSymbolAddress((void**)&y1, g_y1);
    cudaGetSymbolAddress((void**)&y2b, g_y2b);
    cudaGetSymbolAddress((void**)&y3b, g_y3b);
    cudaGetSymbolAddress((void**)&y4b, g_y4b);
    cudaGetSymbolAddress((void**)&y5s, g_y5s);
    cudaGetSymbolAddress((void**)&a1, g_a1);
    cudaGetSymbolAddress((void**)&a2, g_a2);
    cudaGetSymbolAddress((void**)&a3, g_a3);
    cudaGetSymbolAddress((void**)&a4, g_a4);
    cudaGetSymbolAddress((void**)&wp2, g_wp2);
    cudaGetSymbolAddress((void**)&wp3, g_wp3);
    cudaGetSymbolAddress((void**)&wg2, g_wg2);
    cudaGetSymbolAddress((void**)&wg3, g_wg3);
    cudaGetSymbolAddress((void**)&fcwr, g_fcwr);
    cudaGetSymbolAddress((void**)&w1s, g_w1s);

    // Stage 1 (pack_w1 must precede conv1; bn_pool1 is the 4th launch -> profiled)
    pack_w1_kernel<<<12, 256>>>(w1, w1s);
    conv1_kernel<<<dim3(8, BATCH), 256>>>(x, w1s, y1);
    reduce_finalize_kernel<64><<<64, 256>>>(g1, 4096, 512 * 1024);
    bn_pool_sign4_f_kernel<32, 64><<<(512 * 256 * 64 / 4 + 255) / 256, 256>>>(
        y1, a1, b1, 512 * 256 * 64 / 4);

    // weight prep for later stages
    pack_grp_kernel<<<8, 256>>>(w2_1, wg2, 64);
    pack_grp_kernel<<<32, 256>>>(w3_1, wg3, 256);
    pack_sign_kernel<<<64, 256>>>(w2_2, wp2, 256 * 64);
    pack_sign_kernel<<<256, 256>>>(w3_2, wp3, 256 * 256);
    fcw_reorder_kernel<<<640, 256>>>(fcw, fcwr);

    // Stage 2
    conv_grp_kernel<16, 64><<<dim3(16, BATCH), 256>>>(a1, wg2, y2b, 8192);
    reduce_finalize_kernel<64><<<64, 256>>>(g2_1, 8192, 512 * 256);
    bn_sign4_i8_kernel<64><<<(512 * 256 * 64 / 4 + 255) / 256, 256>>>(
        y2b, a2, b2_1, 512 * 256 * 64 / 4);

    gemm64_kernel<<<(512 * 256) / 128, 256>>>(a2, wp2, y3b);
    reduce_finalize_kernel<256><<<256, 256>>>(g2_2, 1024, 512 * 256);
    bn_pool_sign4_i8_kernel<16, 256><<<(512 * 64 * 256 / 4 + 255) / 256, 256>>>(
        y3b, a3, b2_2, 512 * 64 * 256 / 4);

    // Stage 3
    conv_grp_kernel<8, 256><<<dim3(8, BATCH), 256>>>(a3, wg3, y4b, 4096);
    reduce_finalize_kernel<256><<<256, 256>>>(g3_1, 4096, 512 * 64);
    bn_sign4_i8_kernel<256><<<(512 * 64 * 256 / 4 + 255) / 256, 256>>>(
        y4b, a4, b3_1, 512 * 64 * 256 / 4);

    gemm256_kernel<<<(512 * 64) / 64, 256>>>(a4, wp3, y5s);
    reduce_finalize_kernel<256><<<256, 256>>>(g3_2, 512, 512 * 64);

    // FC (bn3_2 fused)
    fc_kernel<<<BATCH / FCB, 256>>>(y5s, fcwr, fcb, b3_2, out);
}